// round 8
// baseline (speedup 1.0000x reference)
#include <cuda_runtime.h>
#include <math.h>

#define SW    192
#define SHW   (192*192)
#define HPX   188
#define NC    32
#define NB    2
#define EPS_F 1e-8f
#define NBLK  (3*24*2)   // grid 3 x 24 x 2

// per-block partial sums — written unconditionally every launch (no zeroing pass)
__device__ double g_part[NBLK];

// Replicates XLA ElementalIrEmitter::EmitExpm1 followed by "+ 1.0":
//   em1 = |x| < 1e-5 ? x + (x*x)*0.5 : exp(x) - 1 ; return em1 + 1
// exp via double (correctly-rounded f32).
__device__ __forceinline__ float xla_expm1_p1(float x) {
    float em1;
    if (fabsf(x) < 1e-5f) {
        em1 = __fadd_rn(x, __fmul_rn(__fmul_rn(x, x), 0.5f));
    } else {
        float e = (float)exp((double)x);
        em1 = __fsub_rn(e, 1.0f);
    }
    return __fadd_rn(em1, 1.0f);
}

__global__ __launch_bounds__(128)
void dgp_kernel(const float* __restrict__ sem, const float* __restrict__ depth) {
    const int tc = blockIdx.x * 16 + threadIdx.x;   // thread-column: 4 x-positions each
    const int r0 = blockIdx.y * 8  + threadIdx.y;   // output row
    const int b  = blockIdx.z;
    const bool valid = (tc < 47) && (r0 < HPX);

    // acc[di][dj][p] : FMA-contracted squared distance (gate value).
    float acc[5][5][4];
    #pragma unroll
    for (int i = 0; i < 5; i++)
        #pragma unroll
        for (int j = 0; j < 5; j++)
            #pragma unroll
            for (int p = 0; p < 4; p++)
                acc[i][j][p] = 0.0f;

    double dsum = 0.0;

    if (valid) {
        const int y  = r0 + 2;
        const int xw = 4 * tc;                       // window start = x0 - 2 (4-aligned)
        const float* __restrict__ base = sem + ((size_t)b * NC) * SHW + y * SW + xw;

        #pragma unroll 1
        for (int ch = 0; ch < NC; ch++) {
            const float* __restrict__ pc = base + ch * SHW;

            // center row (di offset 0) first: provides the 4 center values
            float w[8], ctr[4];
            {
                float4 a0 = *(const float4*)(pc);
                float4 a1 = *(const float4*)(pc + 4);
                w[0]=a0.x; w[1]=a0.y; w[2]=a0.z; w[3]=a0.w;
                w[4]=a1.x; w[5]=a1.y; w[6]=a1.z; w[7]=a1.w;
                #pragma unroll
                for (int p = 0; p < 4; p++) ctr[p] = w[p + 2];
                #pragma unroll
                for (int dj = 0; dj < 5; dj++) {
                    if (dj == 2) continue;           // center_mask (di=2,dj=2)
                    #pragma unroll
                    for (int p = 0; p < 4; p++) {
                        float d = w[p + dj] - ctr[p];
                        acc[2][dj][p] = fmaf(d, d, acc[2][dj][p]);
                    }
                }
            }
            // remaining rows
            #pragma unroll
            for (int di = 0; di < 5; di++) {
                if (di == 2) continue;
                const float* __restrict__ pr = pc + (di - 2) * SW;
                float4 a0 = *(const float4*)(pr);
                float4 a1 = *(const float4*)(pr + 4);
                w[0]=a0.x; w[1]=a0.y; w[2]=a0.z; w[3]=a0.w;
                w[4]=a1.x; w[5]=a1.y; w[6]=a1.z; w[7]=a1.w;
                #pragma unroll
                for (int dj = 0; dj < 5; dj++)
                    #pragma unroll
                    for (int p = 0; p < 4; p++) {
                        float d = w[p + dj] - ctr[p];
                        acc[di][dj][p] = fmaf(d, d, acc[di][dj][p]);
                    }
            }
        }

        // rare precise path: exact XLA-order recompute per qualifying term
        #pragma unroll
        for (int di = 0; di < 5; di++)
            #pragma unroll
            for (int dj = 0; dj < 5; dj++) {
                if (di == 2 && dj == 2) continue;
                #pragma unroll
                for (int p = 0; p < 4; p++) {
                    if (acc[di][dj][p] < 18.5f) {
                        const int xc  = 4 * tc + 2 + p;
                        const int off = (di - 2) * SW + (dj - 2);
                        const float* __restrict__ sp = sem + ((size_t)b * NC) * SHW + y * SW + xc;
                        float s = 0.0f;
                        for (int ch = 0; ch < NC; ch++) {
                            float d = __fsub_rn(sp[ch * SHW + off], sp[ch * SHW]);
                            s = __fadd_rn(s, __fmul_rn(d, d));
                        }
                        float sd  = fmaxf(__fsqrt_rn(s), EPS_F);
                        float ssq = __fmul_rn(sd, sd);
                        const float* __restrict__ dpp = depth + b * SHW + y * SW + xc;
                        float invc = __fdiv_rn(1.0f, __fadd_rn(dpp[0],   1e-6f));
                        float invo = __fdiv_rn(1.0f, __fadd_rn(dpp[off], 1e-6f));
                        float dd   = fmaxf(fabsf(__fsub_rn(invc, invo)), EPS_F);
                        if (dd > EPS_F && sd > EPS_F) {
                            float f1 = xla_expm1_p1(-__fdiv_rn(dd, 10.0f));
                            float f2 = xla_expm1_p1(-ssq);
                            dsum += (double)__fmul_rn(f1, f2);
                        }
                    }
                }
            }
    }

    // block reduction (almost always all-zero) -> per-block slot
    const int tid  = threadIdx.y * 16 + threadIdx.x;
    const int lane = tid & 31, wid = tid >> 5;
    #pragma unroll
    for (int o = 16; o > 0; o >>= 1)
        dsum += __shfl_down_sync(0xffffffffu, dsum, o);

    __shared__ double ws[4];
    if (lane == 0) ws[wid] = dsum;
    __syncthreads();
    if (tid == 0) {
        double t = ws[0] + ws[1] + ws[2] + ws[3];
        g_part[(blockIdx.z * 24 + blockIdx.y) * 3 + blockIdx.x] = t;
    }
}

__global__ void fin_kernel(float* __restrict__ out) {
    const int tid  = threadIdx.x;            // 160 threads (5 warps)
    double v = (tid < NBLK) ? g_part[tid] : 0.0;
    #pragma unroll
    for (int o = 16; o > 0; o >>= 1)
        v += __shfl_down_sync(0xffffffffu, v, o);
    __shared__ double ws[5];
    if ((tid & 31) == 0) ws[tid >> 5] = v;
    __syncthreads();
    if (tid == 0) {
        double s = ws[0] + ws[1] + ws[2] + ws[3] + ws[4];
        // divisor: mean over (B,B,k,k,P): S / (25*B*P) = S / 1,767,200
        out[0] = (float)(s / 1767200.0);
    }
}

extern "C" void kernel_launch(void* const* d_in, const int* in_sizes, int n_in,
                              void* d_out, int out_size) {
    const float* sem   = (const float*)d_in[0];  // (2, 32, 192, 192) f32
    const float* depth = (const float*)d_in[1];  // (2, 1, 192, 192) f32

    dim3 blk(16, 8);
    dim3 grd(3, 24, NB);
    dgp_kernel<<<grd, blk>>>(sem, depth);

    fin_kernel<<<1, 160>>>((float*)d_out);
}

// round 9
// speedup vs baseline: 1.1836x; 1.1836x over previous
#include <cuda_runtime.h>
#include <math.h>

#define SW    192
#define SHW   (192*192)
#define HPX   188
#define NC    32
#define NB    2
#define EPS_F 1e-8f
#define GX    3
#define GY    47
#define NBLK  (GX*GY*NB)   // 282

__device__ double       g_part[NBLK];
__device__ unsigned int g_ctr = 0;

typedef unsigned long long u64;

// ---- packed f32x2 helpers (Blackwell FFMA2 path) ----
__device__ __forceinline__ u64 pack2(float lo, float hi) {
    u64 r; asm("mov.b64 %0, {%1, %2};" : "=l"(r) : "f"(lo), "f"(hi)); return r;
}
__device__ __forceinline__ void unpack2(u64 v, float& lo, float& hi) {
    asm("mov.b64 {%0, %1}, %2;" : "=f"(lo), "=f"(hi) : "l"(v));
}
__device__ __forceinline__ u64 add2(u64 a, u64 b) {
    u64 r; asm("add.rn.f32x2 %0, %1, %2;" : "=l"(r) : "l"(a), "l"(b)); return r;
}
__device__ __forceinline__ u64 fma2(u64 a, u64 b, u64 c) {
    u64 r; asm("fma.rn.f32x2 %0, %1, %2, %3;" : "=l"(r) : "l"(a), "l"(b), "l"(c)); return r;
}

// Replicates XLA EmitExpm1 then "+1.0":
//   em1 = |x| < 1e-5 ? x + (x*x)*0.5 : exp(x) - 1 ; return em1 + 1
// (exp via double = correctly-rounded f32; validated rel_err 0.0 in R7/R8)
__device__ __forceinline__ float xla_expm1_p1(float x) {
    float em1;
    if (fabsf(x) < 1e-5f) {
        em1 = __fadd_rn(x, __fmul_rn(__fmul_rn(x, x), 0.5f));
    } else {
        float e = (float)exp((double)x);
        em1 = __fsub_rn(e, 1.0f);
    }
    return __fadd_rn(em1, 1.0f);
}

__global__ __launch_bounds__(128)
void dgp_kernel(const float* __restrict__ sem, const float* __restrict__ depth,
                float* __restrict__ out) {
    const int tx = threadIdx.x, ty = threadIdx.y;          // block (32, 4)
    const int x0 = 2 * (blockIdx.x * 32 + tx);             // even window start (= xc0 - 2)
    const int r0 = blockIdx.y * 4 + ty;                    // 47*4 = 188 exact
    const int b  = blockIdx.z;
    const bool valid = (x0 < HPX);

    // acc[di][dj] : packed squared distances for positions (x0+2, x0+3)
    u64 acc[5][5];
    #pragma unroll
    for (int i = 0; i < 5; i++)
        #pragma unroll
        for (int j = 0; j < 5; j++)
            acc[i][j] = 0ull;

    double dsum = 0.0;
    const int y = r0 + 2;

    if (valid) {
        const float* __restrict__ base = sem + ((size_t)b * NC) * SHW + y * SW + x0;

        #pragma unroll 1
        for (int ch = 0; ch < NC; ch++) {
            const float* __restrict__ pc = base + ch * SHW;

            // ---- center row (di=2): also yields the negated center pair ----
            float2 c0 = *(const float2*)(pc);
            float2 c1 = *(const float2*)(pc + 2);
            float2 c2 = *(const float2*)(pc + 4);
            const u64 nctr = pack2(-c1.x, -c1.y);          // -(w2, w3)
            {
                u64 d;
                d = add2(pack2(c0.x, c0.y), nctr); acc[2][0] = fma2(d, d, acc[2][0]);
                d = add2(pack2(c0.y, c1.x), nctr); acc[2][1] = fma2(d, d, acc[2][1]);
                /* dj=2 is the masked center: identically 0, skip */
                d = add2(pack2(c1.y, c2.x), nctr); acc[2][3] = fma2(d, d, acc[2][3]);
                d = add2(pack2(c2.x, c2.y), nctr); acc[2][4] = fma2(d, d, acc[2][4]);
            }
            // ---- other 4 rows ----
            #pragma unroll
            for (int di = 0; di < 5; di++) {
                if (di == 2) continue;
                const float* __restrict__ pr = pc + (di - 2) * SW;
                float2 a0 = *(const float2*)(pr);
                float2 a1 = *(const float2*)(pr + 2);
                float2 a2 = *(const float2*)(pr + 4);
                u64 d;
                d = add2(pack2(a0.x, a0.y), nctr); acc[di][0] = fma2(d, d, acc[di][0]);
                d = add2(pack2(a0.y, a1.x), nctr); acc[di][1] = fma2(d, d, acc[di][1]);
                d = add2(pack2(a1.x, a1.y), nctr); acc[di][2] = fma2(d, d, acc[di][2]);
                d = add2(pack2(a1.y, a2.x), nctr); acc[di][3] = fma2(d, d, acc[di][3]);
                d = add2(pack2(a2.x, a2.y), nctr); acc[di][4] = fma2(d, d, acc[di][4]);
            }
        }

        // ---- gate (monotone: contracted acc ~= exact s, margin 18.5 > 18.02 cutoff) ----
        #pragma unroll
        for (int di = 0; di < 5; di++)
            #pragma unroll
            for (int dj = 0; dj < 5; dj++) {
                if (di == 2 && dj == 2) continue;
                float s0, s1;
                unpack2(acc[di][dj], s0, s1);
                #pragma unroll
                for (int p = 0; p < 2; p++) {
                    float sg = p ? s1 : s0;
                    if (sg < 18.5f) {
                        // rare exact XLA-order recompute for this (pos, offset)
                        const int xc  = x0 + 2 + p;
                        const int off = (di - 2) * SW + (dj - 2);
                        const float* __restrict__ sp = sem + ((size_t)b * NC) * SHW + y * SW + xc;
                        float s = 0.0f;
                        for (int ch = 0; ch < NC; ch++) {
                            float d = __fsub_rn(sp[ch * SHW + off], sp[ch * SHW]);
                            s = __fadd_rn(s, __fmul_rn(d, d));
                        }
                        float sd  = fmaxf(__fsqrt_rn(s), EPS_F);
                        float ssq = __fmul_rn(sd, sd);
                        const float* __restrict__ dpp = depth + b * SHW + y * SW + xc;
                        float invc = __fdiv_rn(1.0f, __fadd_rn(dpp[0],   1e-6f));
                        float invo = __fdiv_rn(1.0f, __fadd_rn(dpp[off], 1e-6f));
                        float dd   = fmaxf(fabsf(__fsub_rn(invc, invo)), EPS_F);
                        if (dd > EPS_F && sd > EPS_F) {
                            float f1 = xla_expm1_p1(-__fdiv_rn(dd, 10.0f));
                            float f2 = xla_expm1_p1(-ssq);
                            dsum += (double)__fmul_rn(f1, f2);
                        }
                    }
                }
            }
    }

    // ---- block reduction -> per-block slot ----
    const int tid  = ty * 32 + tx;
    const int lane = tid & 31, wid = tid >> 5;
    #pragma unroll
    for (int o = 16; o > 0; o >>= 1)
        dsum += __shfl_down_sync(0xffffffffu, dsum, o);

    __shared__ double ws[4];
    __shared__ bool   is_last;
    if (lane == 0) ws[wid] = dsum;
    __syncthreads();

    const int bid = (blockIdx.z * GY + blockIdx.y) * GX + blockIdx.x;
    if (tid == 0) {
        g_part[bid] = ws[0] + ws[1] + ws[2] + ws[3];
        __threadfence();
        unsigned old = atomicAdd(&g_ctr, 1u);
        is_last = (old == NBLK - 1);
    }
    __syncthreads();

    // ---- last block finalizes (no separate fin kernel) ----
    if (is_last) {
        double v = 0.0;
        for (int i = tid; i < NBLK; i += 128) v += g_part[i];
        #pragma unroll
        for (int o = 16; o > 0; o >>= 1)
            v += __shfl_down_sync(0xffffffffu, v, o);
        __shared__ double fs[4];
        if (lane == 0) fs[wid] = v;
        __syncthreads();
        if (tid == 0) {
            double s = fs[0] + fs[1] + fs[2] + fs[3];
            // mean over (B,B,k,k,P): S / (25*B*P) = S / 1,767,200
            out[0] = (float)(s / 1767200.0);
            g_ctr  = 0;          // reset for next (graph-replayed) launch
        }
    }
}

extern "C" void kernel_launch(void* const* d_in, const int* in_sizes, int n_in,
                              void* d_out, int out_size) {
    const float* sem   = (const float*)d_in[0];  // (2, 32, 192, 192) f32
    const float* depth = (const float*)d_in[1];  // (2, 1, 192, 192) f32

    dim3 blk(32, 4);
    dim3 grd(GX, GY, NB);
    dgp_kernel<<<grd, blk>>>(sem, depth, (float*)d_out);
}